// round 4
// baseline (speedup 1.0000x reference)
#include <cuda_runtime.h>
#include <cuda_fp16.h>

// Sinkhorn (eps=0.1, 50 iters) on N=8, P1=P2=2048.
// Exp-domain matrix scaling with fp16 K = exp(-C/eps), fully L2-resident (67 MB).
//   a = (mu+1e-8)/(K b);  b = (nu+1e-8)/(K^T a)
// Final pi computed from exact f32 C: pi = a_i * b_j * exp(-C/eps).
//
// R2: rowpass re-tiled 16 rows/warp -> 8 rows/warp (grid 256 -> 512) to fix
// grid starvation (occ 10% -> ~21%, in-flight loads ~3x).

#define NB 8
#define PP 2048
#define M_ELEMS (NB * (size_t)PP * (size_t)PP)   // 33,554,432
#define INV_EPS 10.0f
#define NITER 50
#define LOGEPS 1e-8f

__device__ __half g_K[M_ELEMS];          // 64 MiB scratch
__device__ float  g_a[NB * PP];
__device__ float  g_b[NB * PP];
__device__ float  g_part[4096];

// ---------------------------------------------------------------------------
// Prologue: K = fp16(exp(-C/eps)); init b = 1 (v0 = 0).
// ---------------------------------------------------------------------------
__global__ void __launch_bounds__(256) prologue_kernel(const float* __restrict__ C) {
    size_t tid  = (size_t)blockIdx.x * 256 + threadIdx.x;
    size_t base = tid * 8;
    float4 c0 = *(const float4*)(C + base);
    float4 c1 = *(const float4*)(C + base + 4);
    union { __half2 h2[4]; uint4 u; } pk;
    pk.h2[0] = __floats2half2_rn(__expf(-INV_EPS * c0.x), __expf(-INV_EPS * c0.y));
    pk.h2[1] = __floats2half2_rn(__expf(-INV_EPS * c0.z), __expf(-INV_EPS * c0.w));
    pk.h2[2] = __floats2half2_rn(__expf(-INV_EPS * c1.x), __expf(-INV_EPS * c1.y));
    pk.h2[3] = __floats2half2_rn(__expf(-INV_EPS * c1.z), __expf(-INV_EPS * c1.w));
    *(uint4*)(g_K + base) = pk.u;
    if (tid < (size_t)NB * PP) g_b[tid] = 1.0f;
}

// ---------------------------------------------------------------------------
// Row pass: s_i = sum_j K_ij * b_j;  a_i = (mu_i + 1e-8) / s_i.
// 128 threads (4 warps), 8 rows/warp, 32 rows/CTA. grid = 8*64 = 512.
// Each lane holds its 64 b-values in registers (lane l owns j = it*256 + l*8 + {0..7}).
// ---------------------------------------------------------------------------
__global__ void __launch_bounds__(128) rowpass_kernel(const float* __restrict__ mu) {
    int batch = blockIdx.x >> 6;       // 64 CTAs per batch
    int blk   = blockIdx.x & 63;
    int w = threadIdx.x >> 5;
    int l = threadIdx.x & 31;
    int row0 = blk * 32 + w * 8;

    const float* bptr = g_b + batch * PP;
    float bb[8][8];
#pragma unroll
    for (int it = 0; it < 8; it++) {
        float4 b0 = *(const float4*)(bptr + it * 256 + l * 8);
        float4 b1 = *(const float4*)(bptr + it * 256 + l * 8 + 4);
        bb[it][0] = b0.x; bb[it][1] = b0.y; bb[it][2] = b0.z; bb[it][3] = b0.w;
        bb[it][4] = b1.x; bb[it][5] = b1.y; bb[it][6] = b1.z; bb[it][7] = b1.w;
    }

#pragma unroll 1
    for (int r = 0; r < 8; r++) {
        int row = batch * PP + row0 + r;
        const __half* Krow = g_K + (size_t)row * PP;
        float s0 = 0.f, s1 = 0.f, s2 = 0.f, s3 = 0.f;
#pragma unroll
        for (int it = 0; it < 8; it++) {
            uint4 kv = *(const uint4*)(Krow + it * 256 + l * 8);
            const __half2* h2 = (const __half2*)&kv;
            float2 f0 = __half22float2(h2[0]);
            float2 f1 = __half22float2(h2[1]);
            float2 f2 = __half22float2(h2[2]);
            float2 f3 = __half22float2(h2[3]);
            s0 = fmaf(f0.x, bb[it][0], s0);
            s1 = fmaf(f0.y, bb[it][1], s1);
            s2 = fmaf(f1.x, bb[it][2], s2);
            s3 = fmaf(f1.y, bb[it][3], s3);
            s0 = fmaf(f2.x, bb[it][4], s0);
            s1 = fmaf(f2.y, bb[it][5], s1);
            s2 = fmaf(f3.x, bb[it][6], s2);
            s3 = fmaf(f3.y, bb[it][7], s3);
        }
        float s = (s0 + s1) + (s2 + s3);
#pragma unroll
        for (int off = 16; off; off >>= 1) s += __shfl_xor_sync(0xffffffffu, s, off);
        if (l == 0) g_a[row] = (mu[row] + LOGEPS) / s;
    }
}

// ---------------------------------------------------------------------------
// Col pass: t_j = sum_i K_ij * a_i;  b_j = (nu_j + 1e-8) / t_j.
// 256 threads, CTA owns 16 columns; thread t handles rows t + 256q.
// grid = 8*128 = 1024. No atomics; deterministic tree reduction.
// ---------------------------------------------------------------------------
__global__ void __launch_bounds__(256) colpass_kernel(const float* __restrict__ nu) {
    int batch = blockIdx.x >> 7;
    int cb    = blockIdx.x & 127;
    int j0    = cb * 16;
    int t = threadIdx.x;
    int w = t >> 5, l = t & 31;

    const float* aptr = g_a + batch * PP;
    float acc[16];
#pragma unroll
    for (int c = 0; c < 16; c++) acc[c] = 0.f;

#pragma unroll
    for (int q = 0; q < 8; q++) {
        int r = t + q * 256;
        const __half* p = g_K + ((size_t)(batch * PP + r)) * PP + j0;
        uint4 k0 = *(const uint4*)p;
        uint4 k1 = *(const uint4*)(p + 8);
        float av = aptr[r];
        const __half2* h0 = (const __half2*)&k0;
        const __half2* h1 = (const __half2*)&k1;
#pragma unroll
        for (int c = 0; c < 4; c++) {
            float2 f = __half22float2(h0[c]);
            acc[2 * c + 0] = fmaf(f.x, av, acc[2 * c + 0]);
            acc[2 * c + 1] = fmaf(f.y, av, acc[2 * c + 1]);
        }
#pragma unroll
        for (int c = 0; c < 4; c++) {
            float2 f = __half22float2(h1[c]);
            acc[8 + 2 * c + 0] = fmaf(f.x, av, acc[8 + 2 * c + 0]);
            acc[8 + 2 * c + 1] = fmaf(f.y, av, acc[8 + 2 * c + 1]);
        }
    }

    __shared__ float sm[8][16];
#pragma unroll
    for (int c = 0; c < 16; c++) {
        float v = acc[c];
#pragma unroll
        for (int off = 16; off; off >>= 1) v += __shfl_xor_sync(0xffffffffu, v, off);
        if (l == c) sm[w][c] = v;   // lane c holds the (identical) reduced value
    }
    __syncthreads();
    if (t < 16) {
        float tj = 0.f;
#pragma unroll
        for (int ww = 0; ww < 8; ww++) tj += sm[ww][t];
        int j = batch * PP + j0 + t;
        g_b[j] = (nu[j] + LOGEPS) / tj;
    }
}

// ---------------------------------------------------------------------------
// Epilogue: pi = a_i * b_j * exp(-C/eps) from exact f32 C; copy C; cost partials.
// ---------------------------------------------------------------------------
__global__ void __launch_bounds__(256) epilogue_kernel(const float* __restrict__ C,
                                                       float* __restrict__ pi_out,
                                                       float* __restrict__ c_out) {
    int batch = blockIdx.x >> 9;
    int rb    = blockIdx.x & 511;
    int r0    = rb * 4;
    int t = threadIdx.x;
    int w = t >> 5, l = t & 31;

    const float* arow = g_a + batch * PP + r0;
    const float* bptr = g_b + batch * PP;
    float cost = 0.f;
#pragma unroll
    for (int q = 0; q < 8; q++) {
        int f  = t + q * 256;
        int rl = f >> 9;
        int c4 = f & 511;
        size_t idx = ((size_t)(batch * PP + r0 + rl)) * PP + (size_t)c4 * 4;
        float4 cv = *(const float4*)(C + idx);
        float  a  = arow[rl];
        float4 bv = *(const float4*)(bptr + c4 * 4);
        float4 pv;
        pv.x = a * bv.x * __expf(-INV_EPS * cv.x);
        pv.y = a * bv.y * __expf(-INV_EPS * cv.y);
        pv.z = a * bv.z * __expf(-INV_EPS * cv.z);
        pv.w = a * bv.w * __expf(-INV_EPS * cv.w);
        if (pi_out) *(float4*)(pi_out + idx) = pv;
        if (c_out)  *(float4*)(c_out + idx)  = cv;
        cost += pv.x * cv.x + pv.y * cv.y + pv.z * cv.z + pv.w * cv.w;
    }
#pragma unroll
    for (int off = 16; off; off >>= 1) cost += __shfl_xor_sync(0xffffffffu, cost, off);
    __shared__ float sm[8];
    if (l == 0) sm[w] = cost;
    __syncthreads();
    if (t == 0) {
        float s = 0.f;
#pragma unroll
        for (int i = 0; i < 8; i++) s += sm[i];
        g_part[blockIdx.x] = s;
    }
}

// Final fixed-order cost reduction (deterministic, no float atomics).
__global__ void cost_final_kernel(float* __restrict__ cost_out) {
    int w = threadIdx.x >> 5, l = threadIdx.x & 31;
    float s = 0.f;
#pragma unroll
    for (int m = 0; m < 16; m++) s += g_part[w * 512 + l + m * 32];
#pragma unroll
    for (int off = 16; off; off >>= 1) s += __shfl_xor_sync(0xffffffffu, s, off);
    if (l == 0) cost_out[w] = s;
}

// ---------------------------------------------------------------------------
extern "C" void kernel_launch(void* const* d_in, const int* in_sizes, int n_in,
                              void* d_out, int out_size) {
    const float* C  = (const float*)d_in[0];
    const float* mu = (const float*)d_in[1];
    const float* nu = (const float*)d_in[2];
    float* out = (float*)d_out;

    const long long M  = (long long)M_ELEMS;
    const long long os = (long long)out_size;
    float *cost = nullptr, *pi = nullptr, *cc = nullptr;
    if (os >= 8 + 2 * M)      { cost = out; pi = out + 8; cc = out + 8 + M; }
    else if (os == 2 * M)     { pi = out; cc = out + M; }
    else if (os == M + 8)     { cost = out; pi = out + 8; }
    else if (os == M)         { pi = out; }
    else if (os == 8)         { cost = out; }
    else                      { cost = out; if (os > 8 + M) { pi = out + 8; cc = out + 8 + M; }
                                else if (os > 8) pi = out + 8; }

    prologue_kernel<<<16384, 256>>>(C);
    for (int k = 0; k < NITER; k++) {
        rowpass_kernel<<<512, 128>>>(mu);
        colpass_kernel<<<1024, 256>>>(nu);
    }
    epilogue_kernel<<<4096, 256>>>(C, pi, cc);
    if (cost) cost_final_kernel<<<1, 256>>>(cost);
}

// round 5
// speedup vs baseline: 1.3876x; 1.3876x over previous
#include <cuda_runtime.h>
#include <cuda_fp16.h>

// Sinkhorn (eps=0.1, 50 iters) on N=8, P1=P2=2048.
// Exp-domain matrix scaling with fp16 K = exp(-C/eps) (67 MB, L2-resident).
//   a = (mu+1e-8)/(K b);  b = (nu+1e-8)/(K^T a)
// Final pi from exact f32 C: pi = a_i * b_j * exp(-C/eps).
//
// R5: rowpass redesigned for occupancy — b cached in SMEM (not 64 registers),
// 256-thread CTAs, 2 rows/warp, grid 1024. Target: L2-BW-bound row pass.

#define NB 8
#define PP 2048
#define M_ELEMS (NB * (size_t)PP * (size_t)PP)   // 33,554,432
#define INV_EPS 10.0f
#define NITER 50
#define LOGEPS 1e-8f

__device__ __half g_K[M_ELEMS];          // 64 MiB scratch
__device__ float  g_a[NB * PP];
__device__ float  g_b[NB * PP];
__device__ float  g_part[4096];

// ---------------------------------------------------------------------------
// Prologue: K = fp16(exp(-C/eps)); init b = 1 (v0 = 0).
// ---------------------------------------------------------------------------
__global__ void __launch_bounds__(256) prologue_kernel(const float* __restrict__ C) {
    size_t tid  = (size_t)blockIdx.x * 256 + threadIdx.x;
    size_t base = tid * 8;
    float4 c0 = *(const float4*)(C + base);
    float4 c1 = *(const float4*)(C + base + 4);
    union { __half2 h2[4]; uint4 u; } pk;
    pk.h2[0] = __floats2half2_rn(__expf(-INV_EPS * c0.x), __expf(-INV_EPS * c0.y));
    pk.h2[1] = __floats2half2_rn(__expf(-INV_EPS * c0.z), __expf(-INV_EPS * c0.w));
    pk.h2[2] = __floats2half2_rn(__expf(-INV_EPS * c1.x), __expf(-INV_EPS * c1.y));
    pk.h2[3] = __floats2half2_rn(__expf(-INV_EPS * c1.z), __expf(-INV_EPS * c1.w));
    *(uint4*)(g_K + base) = pk.u;
    if (tid < (size_t)NB * PP) g_b[tid] = 1.0f;
}

// ---------------------------------------------------------------------------
// Row pass v3: s_i = sum_j K_ij * b_j;  a_i = (mu_i + 1e-8) / s_i.
// 256 threads (8 warps), b in SMEM, 2 rows/warp, 16 rows/CTA, grid = 8*128.
// Lane l of a warp covers columns it*256 + l*8 + {0..7}, it = 0..7.
// ---------------------------------------------------------------------------
__global__ void __launch_bounds__(256) rowpass_kernel(const float* __restrict__ mu) {
    __shared__ float b_sm[PP];
    int batch = blockIdx.x >> 7;       // 128 CTAs per batch
    int blk   = blockIdx.x & 127;
    int t = threadIdx.x;
    int w = t >> 5, l = t & 31;

    // Cooperative load of b into smem (2048 floats, 8 per thread).
    {
        const float* bptr = g_b + batch * PP + t * 8;
        float4 v0 = *(const float4*)(bptr);
        float4 v1 = *(const float4*)(bptr + 4);
        *(float4*)(b_sm + t * 8)     = v0;
        *(float4*)(b_sm + t * 8 + 4) = v1;
    }
    __syncthreads();

    int row0 = blk * 16 + w * 2;
#pragma unroll
    for (int r = 0; r < 2; r++) {
        int row = batch * PP + row0 + r;
        const __half* Krow = g_K + (size_t)row * PP;
        float s0 = 0.f, s1 = 0.f, s2 = 0.f, s3 = 0.f;
#pragma unroll
        for (int it = 0; it < 8; it++) {
            uint4 kv = *(const uint4*)(Krow + it * 256 + l * 8);
            float4 b0 = *(const float4*)(b_sm + it * 256 + l * 8);
            float4 b1 = *(const float4*)(b_sm + it * 256 + l * 8 + 4);
            const __half2* h2 = (const __half2*)&kv;
            float2 f0 = __half22float2(h2[0]);
            float2 f1 = __half22float2(h2[1]);
            float2 f2 = __half22float2(h2[2]);
            float2 f3 = __half22float2(h2[3]);
            s0 = fmaf(f0.x, b0.x, s0);
            s1 = fmaf(f0.y, b0.y, s1);
            s2 = fmaf(f1.x, b0.z, s2);
            s3 = fmaf(f1.y, b0.w, s3);
            s0 = fmaf(f2.x, b1.x, s0);
            s1 = fmaf(f2.y, b1.y, s1);
            s2 = fmaf(f3.x, b1.z, s2);
            s3 = fmaf(f3.y, b1.w, s3);
        }
        float s = (s0 + s1) + (s2 + s3);
#pragma unroll
        for (int off = 16; off; off >>= 1) s += __shfl_xor_sync(0xffffffffu, s, off);
        if (l == 0) g_a[row] = (mu[row] + LOGEPS) / s;
    }
}

// ---------------------------------------------------------------------------
// Col pass: t_j = sum_i K_ij * a_i;  b_j = (nu_j + 1e-8) / t_j.
// 256 threads, CTA owns 16 columns; thread t handles rows t + 256q.
// grid = 8*128 = 1024. No atomics; deterministic tree reduction.
// ---------------------------------------------------------------------------
__global__ void __launch_bounds__(256) colpass_kernel(const float* __restrict__ nu) {
    int batch = blockIdx.x >> 7;
    int cb    = blockIdx.x & 127;
    int j0    = cb * 16;
    int t = threadIdx.x;
    int w = t >> 5, l = t & 31;

    const float* aptr = g_a + batch * PP;
    float acc[16];
#pragma unroll
    for (int c = 0; c < 16; c++) acc[c] = 0.f;

#pragma unroll
    for (int q = 0; q < 8; q++) {
        int r = t + q * 256;
        const __half* p = g_K + ((size_t)(batch * PP + r)) * PP + j0;
        uint4 k0 = *(const uint4*)p;
        uint4 k1 = *(const uint4*)(p + 8);
        float av = aptr[r];
        const __half2* h0 = (const __half2*)&k0;
        const __half2* h1 = (const __half2*)&k1;
#pragma unroll
        for (int c = 0; c < 4; c++) {
            float2 f = __half22float2(h0[c]);
            acc[2 * c + 0] = fmaf(f.x, av, acc[2 * c + 0]);
            acc[2 * c + 1] = fmaf(f.y, av, acc[2 * c + 1]);
        }
#pragma unroll
        for (int c = 0; c < 4; c++) {
            float2 f = __half22float2(h1[c]);
            acc[8 + 2 * c + 0] = fmaf(f.x, av, acc[8 + 2 * c + 0]);
            acc[8 + 2 * c + 1] = fmaf(f.y, av, acc[8 + 2 * c + 1]);
        }
    }

    __shared__ float sm[8][16];
#pragma unroll
    for (int c = 0; c < 16; c++) {
        float v = acc[c];
#pragma unroll
        for (int off = 16; off; off >>= 1) v += __shfl_xor_sync(0xffffffffu, v, off);
        if (l == c) sm[w][c] = v;   // lane c holds the (identical) reduced value
    }
    __syncthreads();
    if (t < 16) {
        float tj = 0.f;
#pragma unroll
        for (int ww = 0; ww < 8; ww++) tj += sm[ww][t];
        int j = batch * PP + j0 + t;
        g_b[j] = (nu[j] + LOGEPS) / tj;
    }
}

// ---------------------------------------------------------------------------
// Epilogue: pi = a_i * b_j * exp(-C/eps) from exact f32 C; copy C; cost partials.
// ---------------------------------------------------------------------------
__global__ void __launch_bounds__(256) epilogue_kernel(const float* __restrict__ C,
                                                       float* __restrict__ pi_out,
                                                       float* __restrict__ c_out) {
    int batch = blockIdx.x >> 9;
    int rb    = blockIdx.x & 511;
    int r0    = rb * 4;
    int t = threadIdx.x;
    int w = t >> 5, l = t & 31;

    const float* arow = g_a + batch * PP + r0;
    const float* bptr = g_b + batch * PP;
    float cost = 0.f;
#pragma unroll
    for (int q = 0; q < 8; q++) {
        int f  = t + q * 256;
        int rl = f >> 9;
        int c4 = f & 511;
        size_t idx = ((size_t)(batch * PP + r0 + rl)) * PP + (size_t)c4 * 4;
        float4 cv = *(const float4*)(C + idx);
        float  a  = arow[rl];
        float4 bv = *(const float4*)(bptr + c4 * 4);
        float4 pv;
        pv.x = a * bv.x * __expf(-INV_EPS * cv.x);
        pv.y = a * bv.y * __expf(-INV_EPS * cv.y);
        pv.z = a * bv.z * __expf(-INV_EPS * cv.z);
        pv.w = a * bv.w * __expf(-INV_EPS * cv.w);
        if (pi_out) *(float4*)(pi_out + idx) = pv;
        if (c_out)  *(float4*)(c_out + idx)  = cv;
        cost += pv.x * cv.x + pv.y * cv.y + pv.z * cv.z + pv.w * cv.w;
    }
#pragma unroll
    for (int off = 16; off; off >>= 1) cost += __shfl_xor_sync(0xffffffffu, cost, off);
    __shared__ float sm[8];
    if (l == 0) sm[w] = cost;
    __syncthreads();
    if (t == 0) {
        float s = 0.f;
#pragma unroll
        for (int i = 0; i < 8; i++) s += sm[i];
        g_part[blockIdx.x] = s;
    }
}

// Final fixed-order cost reduction (deterministic, no float atomics).
__global__ void cost_final_kernel(float* __restrict__ cost_out) {
    int w = threadIdx.x >> 5, l = threadIdx.x & 31;
    float s = 0.f;
#pragma unroll
    for (int m = 0; m < 16; m++) s += g_part[w * 512 + l + m * 32];
#pragma unroll
    for (int off = 16; off; off >>= 1) s += __shfl_xor_sync(0xffffffffu, s, off);
    if (l == 0) cost_out[w] = s;
}

// ---------------------------------------------------------------------------
extern "C" void kernel_launch(void* const* d_in, const int* in_sizes, int n_in,
                              void* d_out, int out_size) {
    const float* C  = (const float*)d_in[0];
    const float* mu = (const float*)d_in[1];
    const float* nu = (const float*)d_in[2];
    float* out = (float*)d_out;

    const long long M  = (long long)M_ELEMS;
    const long long os = (long long)out_size;
    float *cost = nullptr, *pi = nullptr, *cc = nullptr;
    if (os >= 8 + 2 * M)      { cost = out; pi = out + 8; cc = out + 8 + M; }
    else if (os == 2 * M)     { pi = out; cc = out + M; }
    else if (os == M + 8)     { cost = out; pi = out + 8; }
    else if (os == M)         { pi = out; }
    else if (os == 8)         { cost = out; }
    else                      { cost = out; if (os > 8 + M) { pi = out + 8; cc = out + 8 + M; }
                                else if (os > 8) pi = out + 8; }

    prologue_kernel<<<16384, 256>>>(C);
    for (int k = 0; k < NITER; k++) {
        rowpass_kernel<<<1024, 256>>>(mu);
        colpass_kernel<<<1024, 256>>>(nu);
    }
    epilogue_kernel<<<4096, 256>>>(C, pi, cc);
    if (cost) cost_final_kernel<<<1, 256>>>(cost);
}

// round 6
// speedup vs baseline: 2.1611x; 1.5575x over previous
#include <cuda_runtime.h>
#include <cuda_fp16.h>
#include <cstdint>

// Sinkhorn (eps=0.1, 50 iters) on N=8, P1=P2=2048.
// Exp-domain matrix scaling, fp16 K = exp(-C/eps) (67 MB, L2-resident).
//   a = (mu+1e-8)/(K b);  b = (nu+1e-8)/(K^T a)
// R6: FUSED iteration kernel. Each CTA bulk-copies (cp.async.bulk) a 16-row
// contiguous K tile (64 KB) into smem, computes s_i -> a_i, then column
// partials t_j from the SAME tile (K read once/iter, not twice). Per-CTA t
// partials reduced by a tiny deterministic fix kernel: b = nu'/sum(t_part).
// No atomics anywhere. Final pi from exact f32 C.

#define NB 8
#define PP 2048
#define M_ELEMS (NB * (size_t)PP * (size_t)PP)   // 33,554,432
#define INV_EPS 10.0f
#define NITER 50
#define LOGEPS 1e-8f
#define ROWS_PER_CTA 16
#define CBS 128                                   // col-pass partial slots per batch
#define TILE_BYTES (ROWS_PER_CTA * PP * 2)        // 65536

__device__ __half g_K[M_ELEMS];                   // 64 MiB
__device__ float  g_a[NB * PP];
__device__ float  g_b[NB * PP];
__device__ float  g_tpart[NB * CBS * PP];         // 8 MiB partials
__device__ float  g_part[4096];

// ---------------- small PTX helpers ----------------
__device__ __forceinline__ uint32_t smem_u32(const void* p) {
    uint32_t a;
    asm("{ .reg .u64 t; cvta.to.shared.u64 t, %1; cvt.u32.u64 %0, t; }" : "=r"(a) : "l"(p));
    return a;
}
__device__ __forceinline__ void mbar_init(uint32_t mbar, uint32_t cnt) {
    asm volatile("mbarrier.init.shared.b64 [%0], %1;" :: "r"(mbar), "r"(cnt) : "memory");
}
__device__ __forceinline__ void mbar_expect_tx(uint32_t mbar, uint32_t bytes) {
    asm volatile("mbarrier.arrive.expect_tx.shared.b64 _, [%0], %1;" :: "r"(mbar), "r"(bytes) : "memory");
}
__device__ __forceinline__ void bulk_g2s(uint32_t dst, const void* src, uint32_t bytes, uint32_t mbar) {
    asm volatile("cp.async.bulk.shared::cta.global.mbarrier::complete_tx::bytes [%0], [%1], %2, [%3];"
                 :: "r"(dst), "l"(src), "r"(bytes), "r"(mbar) : "memory");
}
__device__ __forceinline__ void mbar_wait(uint32_t mbar, uint32_t parity) {
    uint32_t done;
    asm volatile("{\n\t.reg .pred p;\n\t"
                 "mbarrier.try_wait.parity.acquire.cta.shared::cta.b64 p, [%1], %2;\n\t"
                 "selp.b32 %0, 1, 0, p;\n\t}"
                 : "=r"(done) : "r"(mbar), "r"(parity) : "memory");
    if (!done) {
        asm volatile("{\n\t.reg .pred P1;\n\t"
                     "WL_%=:\n\t"
                     "mbarrier.try_wait.parity.acquire.cta.shared::cta.b64 P1, [%0], %1, 0x989680;\n\t"
                     "@P1 bra.uni WD_%=;\n\t"
                     "bra.uni WL_%=;\n\t"
                     "WD_%=:\n\t}"
                     :: "r"(mbar), "r"(parity) : "memory");
    }
}

// ---------------------------------------------------------------------------
// Prologue: K = fp16(exp(-C/eps)); init b = 1.
// ---------------------------------------------------------------------------
__global__ void __launch_bounds__(256) prologue_kernel(const float* __restrict__ C) {
    size_t tid  = (size_t)blockIdx.x * 256 + threadIdx.x;
    size_t base = tid * 8;
    float4 c0 = *(const float4*)(C + base);
    float4 c1 = *(const float4*)(C + base + 4);
    union { __half2 h2[4]; uint4 u; } pk;
    pk.h2[0] = __floats2half2_rn(__expf(-INV_EPS * c0.x), __expf(-INV_EPS * c0.y));
    pk.h2[1] = __floats2half2_rn(__expf(-INV_EPS * c0.z), __expf(-INV_EPS * c0.w));
    pk.h2[2] = __floats2half2_rn(__expf(-INV_EPS * c1.x), __expf(-INV_EPS * c1.y));
    pk.h2[3] = __floats2half2_rn(__expf(-INV_EPS * c1.z), __expf(-INV_EPS * c1.w));
    *(uint4*)(g_K + base) = pk.u;
    if (tid < (size_t)NB * PP) g_b[tid] = 1.0f;
}

// ---------------------------------------------------------------------------
// Fused iteration kernel. grid = 8*128 = 1024 CTAs x 256 threads.
// CTA (batch, cb): rows row0..row0+15 (contiguous 64 KB fp16 tile).
//   Phase A: s[r] = sum_j K[r][j]*b[j]  (thread owns j = 8t..8t+7, b in regs)
//   Reduce -> a[r] = (mu[r]+1e-8)/s[r]  (also written to g_a)
//   Phase B: tpart[j] = sum_r K[r][j]*a[r]  -> g_tpart[batch][cb][j]
// ---------------------------------------------------------------------------
__global__ void __launch_bounds__(256) iter_kernel(const float* __restrict__ mu) {
    extern __shared__ char smem_raw[];
    __half* Kt   = (__half*)smem_raw;                       // 65536 B
    float*  a_sm = (float*)(smem_raw + TILE_BYTES);         // 16 floats
    float*  red  = a_sm + 16;                               // 8*16 floats
    uint64_t* mbar_p = (uint64_t*)(red + 128);              // 8 B (offset 66112, 8-aligned)

    int batch = blockIdx.x >> 7;
    int cb    = blockIdx.x & 127;
    int row0  = cb * ROWS_PER_CTA;
    int t = threadIdx.x;
    int w = t >> 5, l = t & 31;

    uint32_t mbar = smem_u32(mbar_p);
    uint32_t ktad = smem_u32(Kt);

    if (t == 0) mbar_init(mbar, 1);
    __syncthreads();
    if (t == 0) {
        asm volatile("fence.proxy.async.shared::cta;" ::: "memory");
        mbar_expect_tx(mbar, TILE_BYTES);
        const __half* src = g_K + ((size_t)(batch * PP + row0)) * PP;
        bulk_g2s(ktad,                 src,                 TILE_BYTES / 2, mbar);
        bulk_g2s(ktad + TILE_BYTES/2, src + (TILE_BYTES/4), TILE_BYTES / 2, mbar);
    }

    // b into registers while the bulk copy is in flight (thread owns cols 8t..8t+7)
    const float* bp = g_b + batch * PP + t * 8;
    float4 bv0 = *(const float4*)(bp);
    float4 bv1 = *(const float4*)(bp + 4);
    float br[8] = { bv0.x, bv0.y, bv0.z, bv0.w, bv1.x, bv1.y, bv1.z, bv1.w };

    mbar_wait(mbar, 0);

    // ---- Phase A: row sums ----
    float s[ROWS_PER_CTA];
#pragma unroll
    for (int r = 0; r < ROWS_PER_CTA; r++) s[r] = 0.f;
#pragma unroll
    for (int r = 0; r < ROWS_PER_CTA; r++) {
        uint4 kv = *(const uint4*)(Kt + r * PP + t * 8);
        const __half2* h2 = (const __half2*)&kv;
        float2 f0 = __half22float2(h2[0]);
        float2 f1 = __half22float2(h2[1]);
        float2 f2 = __half22float2(h2[2]);
        float2 f3 = __half22float2(h2[3]);
        float p0 = fmaf(f0.x, br[0], f0.y * br[1]);
        float p1 = fmaf(f1.x, br[2], f1.y * br[3]);
        float p2 = fmaf(f2.x, br[4], f2.y * br[5]);
        float p3 = fmaf(f3.x, br[6], f3.y * br[7]);
        s[r] = (p0 + p1) + (p2 + p3);
    }

    // reduce each row over 256 threads
#pragma unroll
    for (int r = 0; r < ROWS_PER_CTA; r++) {
        float v = s[r];
#pragma unroll
        for (int off = 16; off; off >>= 1) v += __shfl_xor_sync(0xffffffffu, v, off);
        if (l == 0) red[w * 16 + r] = v;
    }
    __syncthreads();
    if (t < ROWS_PER_CTA) {
        float ss = 0.f;
#pragma unroll
        for (int ww = 0; ww < 8; ww++) ss += red[ww * 16 + t];
        int row = batch * PP + row0 + t;
        float av = (mu[row] + LOGEPS) / ss;
        a_sm[t] = av;
        g_a[row] = av;
    }
    __syncthreads();

    // ---- Phase B: column partials ----
    float acc[8];
#pragma unroll
    for (int c = 0; c < 8; c++) acc[c] = 0.f;
#pragma unroll
    for (int r = 0; r < ROWS_PER_CTA; r++) {
        uint4 kv = *(const uint4*)(Kt + r * PP + t * 8);
        float av = a_sm[r];
        const __half2* h2 = (const __half2*)&kv;
        float2 f0 = __half22float2(h2[0]);
        float2 f1 = __half22float2(h2[1]);
        float2 f2 = __half22float2(h2[2]);
        float2 f3 = __half22float2(h2[3]);
        acc[0] = fmaf(f0.x, av, acc[0]);
        acc[1] = fmaf(f0.y, av, acc[1]);
        acc[2] = fmaf(f1.x, av, acc[2]);
        acc[3] = fmaf(f1.y, av, acc[3]);
        acc[4] = fmaf(f2.x, av, acc[4]);
        acc[5] = fmaf(f2.y, av, acc[5]);
        acc[6] = fmaf(f3.x, av, acc[6]);
        acc[7] = fmaf(f3.y, av, acc[7]);
    }
    float* tp = g_tpart + ((size_t)(batch * CBS + cb)) * PP + t * 8;
    *(float4*)(tp)     = make_float4(acc[0], acc[1], acc[2], acc[3]);
    *(float4*)(tp + 4) = make_float4(acc[4], acc[5], acc[6], acc[7]);
}

// ---------------------------------------------------------------------------
// Fix kernel: t_j = sum_cb tpart[batch][cb][j];  b_j = (nu_j+1e-8)/t_j.
// grid = 8*8 = 64 CTAs x 256 threads; thread owns one j. Fixed-order sums.
// ---------------------------------------------------------------------------
__global__ void __launch_bounds__(256) fix_kernel(const float* __restrict__ nu) {
    int batch = blockIdx.x >> 3;
    int seg   = blockIdx.x & 7;
    int j     = seg * 256 + threadIdx.x;
    const float* tp = g_tpart + (size_t)batch * CBS * PP + j;
    float acc[16];
#pragma unroll
    for (int m = 0; m < 16; m++) acc[m] = 0.f;
#pragma unroll 1
    for (int q = 0; q < 8; q++) {
#pragma unroll
        for (int m = 0; m < 16; m++)
            acc[m] += tp[(size_t)(q * 16 + m) * PP];
    }
    float tj = 0.f;
#pragma unroll
    for (int m = 0; m < 16; m++) tj += acc[m];
    int jj = batch * PP + j;
    g_b[jj] = (nu[jj] + LOGEPS) / tj;
}

// ---------------------------------------------------------------------------
// Epilogue: pi = a_i * b_j * exp(-C/eps) from exact f32 C; copy C; cost partials.
// ---------------------------------------------------------------------------
__global__ void __launch_bounds__(256) epilogue_kernel(const float* __restrict__ C,
                                                       float* __restrict__ pi_out,
                                                       float* __restrict__ c_out) {
    int batch = blockIdx.x >> 9;
    int rb    = blockIdx.x & 511;
    int r0    = rb * 4;
    int t = threadIdx.x;
    int w = t >> 5, l = t & 31;

    const float* arow = g_a + batch * PP + r0;
    const float* bptr = g_b + batch * PP;
    float cost = 0.f;
#pragma unroll
    for (int q = 0; q < 8; q++) {
        int f  = t + q * 256;
        int rl = f >> 9;
        int c4 = f & 511;
        size_t idx = ((size_t)(batch * PP + r0 + rl)) * PP + (size_t)c4 * 4;
        float4 cv = *(const float4*)(C + idx);
        float  a  = arow[rl];
        float4 bv = *(const float4*)(bptr + c4 * 4);
        float4 pv;
        pv.x = a * bv.x * __expf(-INV_EPS * cv.x);
        pv.y = a * bv.y * __expf(-INV_EPS * cv.y);
        pv.z = a * bv.z * __expf(-INV_EPS * cv.z);
        pv.w = a * bv.w * __expf(-INV_EPS * cv.w);
        if (pi_out) *(float4*)(pi_out + idx) = pv;
        if (c_out)  *(float4*)(c_out + idx)  = cv;
        cost += pv.x * cv.x + pv.y * cv.y + pv.z * cv.z + pv.w * cv.w;
    }
#pragma unroll
    for (int off = 16; off; off >>= 1) cost += __shfl_xor_sync(0xffffffffu, cost, off);
    __shared__ float sm[8];
    if (l == 0) sm[w] = cost;
    __syncthreads();
    if (t == 0) {
        float sv = 0.f;
#pragma unroll
        for (int i = 0; i < 8; i++) sv += sm[i];
        g_part[blockIdx.x] = sv;
    }
}

// Final fixed-order cost reduction.
__global__ void cost_final_kernel(float* __restrict__ cost_out) {
    int w = threadIdx.x >> 5, l = threadIdx.x & 31;
    float s = 0.f;
#pragma unroll
    for (int m = 0; m < 16; m++) s += g_part[w * 512 + l + m * 32];
#pragma unroll
    for (int off = 16; off; off >>= 1) s += __shfl_xor_sync(0xffffffffu, s, off);
    if (l == 0) cost_out[w] = s;
}

// ---------------------------------------------------------------------------
#define ITER_SMEM (TILE_BYTES + 64 + 512 + 64)   // 66176 B

extern "C" void kernel_launch(void* const* d_in, const int* in_sizes, int n_in,
                              void* d_out, int out_size) {
    const float* C  = (const float*)d_in[0];
    const float* mu = (const float*)d_in[1];
    const float* nu = (const float*)d_in[2];
    float* out = (float*)d_out;

    static bool attr_set = false;
    if (!attr_set) {
        cudaFuncSetAttribute(iter_kernel, cudaFuncAttributeMaxDynamicSharedMemorySize, ITER_SMEM);
        attr_set = true;
    }

    const long long M  = (long long)M_ELEMS;
    const long long os = (long long)out_size;
    float *cost = nullptr, *pi = nullptr, *cc = nullptr;
    if (os >= 8 + 2 * M)      { cost = out; pi = out + 8; cc = out + 8 + M; }
    else if (os == 2 * M)     { pi = out; cc = out + M; }
    else if (os == M + 8)     { cost = out; pi = out + 8; }
    else if (os == M)         { pi = out; }
    else if (os == 8)         { cost = out; }
    else                      { cost = out; if (os > 8 + M) { pi = out + 8; cc = out + 8 + M; }
                                else if (os > 8) pi = out + 8; }

    prologue_kernel<<<16384, 256>>>(C);
    for (int k = 0; k < NITER; k++) {
        iter_kernel<<<1024, 256, ITER_SMEM>>>(mu);
        fix_kernel<<<64, 256>>>(nu);
    }
    epilogue_kernel<<<4096, 256>>>(C, pi, cc);
    if (cost) cost_final_kernel<<<1, 256>>>(cost);
}

// round 7
// speedup vs baseline: 2.2089x; 1.0221x over previous
#include <cuda_runtime.h>
#include <cuda_fp16.h>
#include <cstdint>

// Sinkhorn (eps=0.1, 50 iters) on N=8, P1=P2=2048.
// Exp-domain matrix scaling, fp16 K = exp(-C/eps) (67 MB, L2-resident).
//   a = (mu+1e-8)/(K b);  b = (nu+1e-8)/(K^T a)
// R7: iter kernel pipelines the 64 KB tile copy as 4 x 16 KB chunks with
// per-chunk mbarriers; phase A starts on chunk 0 while chunks 1..3 stream.
// K read once/iter; per-CTA column partials; deterministic fix kernel.

#define NB 8
#define PP 2048
#define M_ELEMS (NB * (size_t)PP * (size_t)PP)   // 33,554,432
#define INV_EPS 10.0f
#define NITER 50
#define LOGEPS 1e-8f
#define ROWS_PER_CTA 16
#define CBS 128                                   // col-pass partial slots per batch
#define TILE_BYTES (ROWS_PER_CTA * PP * 2)        // 65536
#define NCHUNK 4
#define CHUNK_ROWS (ROWS_PER_CTA / NCHUNK)        // 4
#define CHUNK_BYTES (TILE_BYTES / NCHUNK)         // 16384

__device__ __half g_K[M_ELEMS];                   // 64 MiB
__device__ float  g_a[NB * PP];
__device__ float  g_b[NB * PP];
__device__ float  g_tpart[NB * CBS * PP];         // 8 MiB partials
__device__ float  g_part[4096];

// ---------------- small PTX helpers ----------------
__device__ __forceinline__ uint32_t smem_u32(const void* p) {
    uint32_t a;
    asm("{ .reg .u64 t; cvta.to.shared.u64 t, %1; cvt.u32.u64 %0, t; }" : "=r"(a) : "l"(p));
    return a;
}
__device__ __forceinline__ void mbar_init(uint32_t mbar, uint32_t cnt) {
    asm volatile("mbarrier.init.shared.b64 [%0], %1;" :: "r"(mbar), "r"(cnt) : "memory");
}
__device__ __forceinline__ void mbar_expect_tx(uint32_t mbar, uint32_t bytes) {
    asm volatile("mbarrier.arrive.expect_tx.shared.b64 _, [%0], %1;" :: "r"(mbar), "r"(bytes) : "memory");
}
__device__ __forceinline__ void bulk_g2s(uint32_t dst, const void* src, uint32_t bytes, uint32_t mbar) {
    asm volatile("cp.async.bulk.shared::cta.global.mbarrier::complete_tx::bytes [%0], [%1], %2, [%3];"
                 :: "r"(dst), "l"(src), "r"(bytes), "r"(mbar) : "memory");
}
__device__ __forceinline__ void mbar_wait(uint32_t mbar, uint32_t parity) {
    uint32_t done;
    asm volatile("{\n\t.reg .pred p;\n\t"
                 "mbarrier.try_wait.parity.acquire.cta.shared::cta.b64 p, [%1], %2;\n\t"
                 "selp.b32 %0, 1, 0, p;\n\t}"
                 : "=r"(done) : "r"(mbar), "r"(parity) : "memory");
    if (!done) {
        asm volatile("{\n\t.reg .pred P1;\n\t"
                     "WL_%=:\n\t"
                     "mbarrier.try_wait.parity.acquire.cta.shared::cta.b64 P1, [%0], %1, 0x989680;\n\t"
                     "@P1 bra.uni WD_%=;\n\t"
                     "bra.uni WL_%=;\n\t"
                     "WD_%=:\n\t}"
                     :: "r"(mbar), "r"(parity) : "memory");
    }
}

// ---------------------------------------------------------------------------
// Prologue: K = fp16(exp(-C/eps)); init b = 1.
// ---------------------------------------------------------------------------
__global__ void __launch_bounds__(256) prologue_kernel(const float* __restrict__ C) {
    size_t tid  = (size_t)blockIdx.x * 256 + threadIdx.x;
    size_t base = tid * 8;
    float4 c0 = *(const float4*)(C + base);
    float4 c1 = *(const float4*)(C + base + 4);
    union { __half2 h2[4]; uint4 u; } pk;
    pk.h2[0] = __floats2half2_rn(__expf(-INV_EPS * c0.x), __expf(-INV_EPS * c0.y));
    pk.h2[1] = __floats2half2_rn(__expf(-INV_EPS * c0.z), __expf(-INV_EPS * c0.w));
    pk.h2[2] = __floats2half2_rn(__expf(-INV_EPS * c1.x), __expf(-INV_EPS * c1.y));
    pk.h2[3] = __floats2half2_rn(__expf(-INV_EPS * c1.z), __expf(-INV_EPS * c1.w));
    *(uint4*)(g_K + base) = pk.u;
    if (tid < (size_t)NB * PP) g_b[tid] = 1.0f;
}

// ---------------------------------------------------------------------------
// Fused iteration kernel. grid = 8*128 = 1024 CTAs x 256 threads.
// CTA (batch, cb): rows row0..row0+15, streamed in as 4 x 16 KB chunks.
//   Phase A: s[r] = sum_j K[r][j]*b[j]  (chunk-pipelined; thread owns 8 cols)
//   Reduce -> a[r] = (mu[r]+1e-8)/s[r]  (also written to g_a)
//   Phase B: tpart[j] = sum_r K[r][j]*a[r]  -> g_tpart[batch][cb][j]
// ---------------------------------------------------------------------------
__global__ void __launch_bounds__(256) iter_kernel(const float* __restrict__ mu) {
    extern __shared__ char smem_raw[];
    __half* Kt   = (__half*)smem_raw;                       // 65536 B
    float*  a_sm = (float*)(smem_raw + TILE_BYTES);         // 16 floats
    float*  red  = a_sm + 16;                               // 8*16 floats
    uint64_t* mbar_p = (uint64_t*)(red + 128);              // 4 mbarriers

    int batch = blockIdx.x >> 7;
    int cb    = blockIdx.x & 127;
    int row0  = cb * ROWS_PER_CTA;
    int t = threadIdx.x;
    int w = t >> 5, l = t & 31;

    uint32_t mbar0 = smem_u32(mbar_p);
    uint32_t ktad  = smem_u32(Kt);

    if (t == 0) {
#pragma unroll
        for (int c = 0; c < NCHUNK; c++) mbar_init(mbar0 + c * 8, 1);
    }
    __syncthreads();
    if (t == 0) {
        asm volatile("fence.proxy.async.shared::cta;" ::: "memory");
        const __half* src = g_K + ((size_t)(batch * PP + row0)) * PP;
#pragma unroll
        for (int c = 0; c < NCHUNK; c++) {
            mbar_expect_tx(mbar0 + c * 8, CHUNK_BYTES);
            bulk_g2s(ktad + c * CHUNK_BYTES,
                     src + (size_t)c * (CHUNK_BYTES / 2),
                     CHUNK_BYTES, mbar0 + c * 8);
        }
    }

    // b into registers while the bulk copies are in flight (thread owns cols 8t..8t+7)
    const float* bp = g_b + batch * PP + t * 8;
    float4 bv0 = *(const float4*)(bp);
    float4 bv1 = *(const float4*)(bp + 4);
    float br[8] = { bv0.x, bv0.y, bv0.z, bv0.w, bv1.x, bv1.y, bv1.z, bv1.w };

    // ---- Phase A: row sums, chunk-pipelined ----
    float s[ROWS_PER_CTA];
#pragma unroll
    for (int c = 0; c < NCHUNK; c++) {
        mbar_wait(mbar0 + c * 8, 0);
#pragma unroll
        for (int r4 = 0; r4 < CHUNK_ROWS; r4++) {
            int r = c * CHUNK_ROWS + r4;
            uint4 kv = *(const uint4*)(Kt + r * PP + t * 8);
            const __half2* h2 = (const __half2*)&kv;
            float2 f0 = __half22float2(h2[0]);
            float2 f1 = __half22float2(h2[1]);
            float2 f2 = __half22float2(h2[2]);
            float2 f3 = __half22float2(h2[3]);
            float p0 = fmaf(f0.x, br[0], f0.y * br[1]);
            float p1 = fmaf(f1.x, br[2], f1.y * br[3]);
            float p2 = fmaf(f2.x, br[4], f2.y * br[5]);
            float p3 = fmaf(f3.x, br[6], f3.y * br[7]);
            s[r] = (p0 + p1) + (p2 + p3);
        }
    }

    // reduce each row over 256 threads
#pragma unroll
    for (int r = 0; r < ROWS_PER_CTA; r++) {
        float v = s[r];
#pragma unroll
        for (int off = 16; off; off >>= 1) v += __shfl_xor_sync(0xffffffffu, v, off);
        if (l == 0) red[w * 16 + r] = v;
    }
    __syncthreads();
    if (t < ROWS_PER_CTA) {
        float ss = 0.f;
#pragma unroll
        for (int ww = 0; ww < 8; ww++) ss += red[ww * 16 + t];
        int row = batch * PP + row0 + t;
        float av = (mu[row] + LOGEPS) / ss;
        a_sm[t] = av;
        g_a[row] = av;
    }
    __syncthreads();

    // ---- Phase B: column partials (tile fully smem-resident) ----
    float acc[8];
#pragma unroll
    for (int c = 0; c < 8; c++) acc[c] = 0.f;
#pragma unroll
    for (int r = 0; r < ROWS_PER_CTA; r++) {
        uint4 kv = *(const uint4*)(Kt + r * PP + t * 8);
        float av = a_sm[r];
        const __half2* h2 = (const __half2*)&kv;
        float2 f0 = __half22float2(h2[0]);
        float2 f1 = __half22float2(h2[1]);
        float2 f2 = __half22float2(h2[2]);
        float2 f3 = __half22float2(h2[3]);
        acc[0] = fmaf(f0.x, av, acc[0]);
        acc[1] = fmaf(f0.y, av, acc[1]);
        acc[2] = fmaf(f1.x, av, acc[2]);
        acc[3] = fmaf(f1.y, av, acc[3]);
        acc[4] = fmaf(f2.x, av, acc[4]);
        acc[5] = fmaf(f2.y, av, acc[5]);
        acc[6] = fmaf(f3.x, av, acc[6]);
        acc[7] = fmaf(f3.y, av, acc[7]);
    }
    float* tp = g_tpart + ((size_t)(batch * CBS + cb)) * PP + t * 8;
    *(float4*)(tp)     = make_float4(acc[0], acc[1], acc[2], acc[3]);
    *(float4*)(tp + 4) = make_float4(acc[4], acc[5], acc[6], acc[7]);
}

// ---------------------------------------------------------------------------
// Fix kernel: t_j = sum_cb tpart[batch][cb][j];  b_j = (nu_j+1e-8)/t_j.
// grid = 8*8 = 64 CTAs x 256 threads; thread owns one j. Fixed-order sums.
// ---------------------------------------------------------------------------
__global__ void __launch_bounds__(256) fix_kernel(const float* __restrict__ nu) {
    int batch = blockIdx.x >> 3;
    int seg   = blockIdx.x & 7;
    int j     = seg * 256 + threadIdx.x;
    const float* tp = g_tpart + (size_t)batch * CBS * PP + j;
    float acc[16];
#pragma unroll
    for (int m = 0; m < 16; m++) acc[m] = 0.f;
#pragma unroll 1
    for (int q = 0; q < 8; q++) {
#pragma unroll
        for (int m = 0; m < 16; m++)
            acc[m] += tp[(size_t)(q * 16 + m) * PP];
    }
    float tj = 0.f;
#pragma unroll
    for (int m = 0; m < 16; m++) tj += acc[m];
    int jj = batch * PP + j;
    g_b[jj] = (nu[jj] + LOGEPS) / tj;
}

// ---------------------------------------------------------------------------
// Epilogue: pi = a_i * b_j * exp(-C/eps) from exact f32 C; copy C; cost partials.
// ---------------------------------------------------------------------------
__global__ void __launch_bounds__(256) epilogue_kernel(const float* __restrict__ C,
                                                       float* __restrict__ pi_out,
                                                       float* __restrict__ c_out) {
    int batch = blockIdx.x >> 9;
    int rb    = blockIdx.x & 511;
    int r0    = rb * 4;
    int t = threadIdx.x;
    int w = t >> 5, l = t & 31;

    const float* arow = g_a + batch * PP + r0;
    const float* bptr = g_b + batch * PP;
    float cost = 0.f;
#pragma unroll
    for (int q = 0; q < 8; q++) {
        int f  = t + q * 256;
        int rl = f >> 9;
        int c4 = f & 511;
        size_t idx = ((size_t)(batch * PP + r0 + rl)) * PP + (size_t)c4 * 4;
        float4 cv = *(const float4*)(C + idx);
        float  a  = arow[rl];
        float4 bv = *(const float4*)(bptr + c4 * 4);
        float4 pv;
        pv.x = a * bv.x * __expf(-INV_EPS * cv.x);
        pv.y = a * bv.y * __expf(-INV_EPS * cv.y);
        pv.z = a * bv.z * __expf(-INV_EPS * cv.z);
        pv.w = a * bv.w * __expf(-INV_EPS * cv.w);
        if (pi_out) *(float4*)(pi_out + idx) = pv;
        if (c_out)  *(float4*)(c_out + idx)  = cv;
        cost += pv.x * cv.x + pv.y * cv.y + pv.z * cv.z + pv.w * cv.w;
    }
#pragma unroll
    for (int off = 16; off; off >>= 1) cost += __shfl_xor_sync(0xffffffffu, cost, off);
    __shared__ float sm[8];
    if (l == 0) sm[w] = cost;
    __syncthreads();
    if (t == 0) {
        float sv = 0.f;
#pragma unroll
        for (int i = 0; i < 8; i++) sv += sm[i];
        g_part[blockIdx.x] = sv;
    }
}

// Final fixed-order cost reduction.
__global__ void cost_final_kernel(float* __restrict__ cost_out) {
    int w = threadIdx.x >> 5, l = threadIdx.x & 31;
    float s = 0.f;
#pragma unroll
    for (int m = 0; m < 16; m++) s += g_part[w * 512 + l + m * 32];
#pragma unroll
    for (int off = 16; off; off >>= 1) s += __shfl_xor_sync(0xffffffffu, s, off);
    if (l == 0) cost_out[w] = s;
}

// ---------------------------------------------------------------------------
#define ITER_SMEM (TILE_BYTES + 64 + 512 + 64)   // 66176 B

extern "C" void kernel_launch(void* const* d_in, const int* in_sizes, int n_in,
                              void* d_out, int out_size) {
    const float* C  = (const float*)d_in[0];
    const float* mu = (const float*)d_in[1];
    const float* nu = (const float*)d_in[2];
    float* out = (float*)d_out;

    static bool attr_set = false;
    if (!attr_set) {
        cudaFuncSetAttribute(iter_kernel, cudaFuncAttributeMaxDynamicSharedMemorySize, ITER_SMEM);
        attr_set = true;
    }

    const long long M  = (long long)M_ELEMS;
    const long long os = (long long)out_size;
    float *cost = nullptr, *pi = nullptr, *cc = nullptr;
    if (os >= 8 + 2 * M)      { cost = out; pi = out + 8; cc = out + 8 + M; }
    else if (os == 2 * M)     { pi = out; cc = out + M; }
    else if (os == M + 8)     { cost = out; pi = out + 8; }
    else if (os == M)         { pi = out; }
    else if (os == 8)         { cost = out; }
    else                      { cost = out; if (os > 8 + M) { pi = out + 8; cc = out + 8 + M; }
                                else if (os > 8) pi = out + 8; }

    prologue_kernel<<<16384, 256>>>(C);
    for (int k = 0; k < NITER; k++) {
        iter_kernel<<<1024, 256, ITER_SMEM>>>(mu);
        fix_kernel<<<64, 256>>>(nu);
    }
    epilogue_kernel<<<4096, 256>>>(C, pi, cc);
    if (cost) cost_final_kernel<<<1, 256>>>(cost);
}